// round 14
// baseline (speedup 1.0000x reference)
#include <cuda_runtime.h>
#include <cuda_bf16.h>
#include <math.h>

#define T_TOK 512
#define DM    512
#define DE    1024
#define NE    64
#define NPAIR 1024
#define CHMAX 128
#define CH    32
#define KSTR  40          // smem row stride in bf16 (80 B) -> conflict-free frags

// ---------------- scratch (static device globals; no allocation) ----------------
__device__ float g_probs[T_TOK * NE];
__device__ int   g_topidx[NPAIR];
__device__ float g_topw[NPAIR];
__device__ int   g_rowTok[NPAIR];
__device__ float g_rowW[NPAIR];
__device__ int   g_chunkE[CHMAX], g_chunkB[CHMAX], g_chunkN[CHMAX];
__device__ int   g_nch;
__device__ __nv_bfloat16 g_xhi[T_TOK * DM];
__device__ __nv_bfloat16 g_xlo[T_TOK * DM];
__device__ __nv_bfloat16 g_hhi[(size_t)NPAIR * DE];
__device__ __nv_bfloat16 g_hlo[(size_t)NPAIR * DE];

// ---------------- helpers ----------------
__device__ __forceinline__ unsigned pkbf2(float lo, float hi) {
    unsigned r;
    asm("cvt.rn.bf16x2.f32 %0, %1, %2;" : "=r"(r) : "f"(hi), "f"(lo));
    return r;
}
__device__ __forceinline__ void split4(float4 v, unsigned& h0, unsigned& h1,
                                       unsigned& l0, unsigned& l1) {
    h0 = pkbf2(v.x, v.y);
    h1 = pkbf2(v.z, v.w);
    float rx = v.x - __uint_as_float(h0 << 16);
    float ry = v.y - __uint_as_float(h0 & 0xffff0000u);
    float rz = v.z - __uint_as_float(h1 << 16);
    float rw = v.w - __uint_as_float(h1 & 0xffff0000u);
    l0 = pkbf2(rx, ry);
    l1 = pkbf2(rz, rw);
}
__device__ __forceinline__ void mma16816(float* d, const unsigned* a, const unsigned* b) {
    asm volatile(
        "mma.sync.aligned.m16n8k16.row.col.f32.bf16.bf16.f32 "
        "{%0,%1,%2,%3}, {%4,%5,%6,%7}, {%8,%9}, {%0,%1,%2,%3};"
        : "+f"(d[0]), "+f"(d[1]), "+f"(d[2]), "+f"(d[3])
        : "r"(a[0]), "r"(a[1]), "r"(a[2]), "r"(a[3]), "r"(b[0]), "r"(b[1]));
}
__device__ __forceinline__ void cpa16(char* smem_dst, const void* gsrc) {
    unsigned a = (unsigned)__cvta_generic_to_shared(smem_dst);
    asm volatile("cp.async.cg.shared.global [%0], [%1], 16;" :: "r"(a), "l"(gsrc));
}
#define CPA_COMMIT() asm volatile("cp.async.commit_group;" ::: "memory")
#define CPA_WAIT0()  asm volatile("cp.async.wait_group 0;" ::: "memory")

// ---------------- kernel 0: x -> bf16 hi/lo ----------------
__global__ __launch_bounds__(256) void xcvt_kernel(const float* __restrict__ x) {
    int i = blockIdx.x * 256 + threadIdx.x;      // over 65536 float4s
    float4 v = ((const float4*)x)[i];
    unsigned h0, h1, l0, l1;
    split4(v, h0, h1, l0, l1);
    ((uint2*)g_xhi)[i] = make_uint2(h0, h1);
    ((uint2*)g_xlo)[i] = make_uint2(l0, l1);
}

// ---------------- kernel 1: router (4 tokens per block) ----------------
__global__ __launch_bounds__(256) void router_kernel(const float* __restrict__ x,
                                                     const float* __restrict__ rw) {
    __shared__ float xs[4 * DM];
    __shared__ float lg[4 * NE];
    int tid = threadIdx.x, lane = tid & 31, warp = tid >> 5;
    int tbase = blockIdx.x * 4;

    for (int i = tid; i < 4 * DM / 4; i += 256)
        *(float4*)(xs + i * 4) = *(const float4*)(x + (size_t)tbase * DM + i * 4);
    __syncthreads();

    for (int j = 0; j < 8; j++) {
        int e = warp * 8 + j;
        const float* w = rw + (size_t)e * DM;
        float acc[4] = {0.f, 0.f, 0.f, 0.f};
        #pragma unroll
        for (int q = 0; q < 4; q++) {
            float4 wv = *(const float4*)(w + (size_t)(lane + 32 * q) * 4);
            int kb = (lane + 32 * q) * 4;
            #pragma unroll
            for (int t = 0; t < 4; t++) {
                acc[t] += wv.x * xs[t * DM + kb + 0];
                acc[t] += wv.y * xs[t * DM + kb + 1];
                acc[t] += wv.z * xs[t * DM + kb + 2];
                acc[t] += wv.w * xs[t * DM + kb + 3];
            }
        }
        #pragma unroll
        for (int t = 0; t < 4; t++) {
            float a = acc[t];
            #pragma unroll
            for (int off = 16; off; off >>= 1) a += __shfl_xor_sync(0xffffffffu, a, off);
            if (lane == 0) lg[t * NE + e] = a;
        }
    }
    __syncthreads();

    if (warp < 4) {
        int tl = warp;
        int t = tbase + tl;
        float l0 = lg[tl * NE + lane];
        float l1 = lg[tl * NE + lane + 32];
        float m = fmaxf(l0, l1);
        #pragma unroll
        for (int off = 16; off; off >>= 1) m = fmaxf(m, __shfl_xor_sync(0xffffffffu, m, off));
        float p0 = expf(l0 - m), p1 = expf(l1 - m);
        float s = p0 + p1;
        #pragma unroll
        for (int off = 16; off; off >>= 1) s += __shfl_xor_sync(0xffffffffu, s, off);
        g_probs[(size_t)t * NE + lane]      = p0 / s;
        g_probs[(size_t)t * NE + lane + 32] = p1 / s;

        float v; int ix;
        if (l1 > l0) { v = l1; ix = lane + 32; } else { v = l0; ix = lane; }
        #pragma unroll
        for (int off = 16; off; off >>= 1) {
            float ov = __shfl_xor_sync(0xffffffffu, v, off);
            int   oi = __shfl_xor_sync(0xffffffffu, ix, off);
            if (ov > v || (ov == v && oi < ix)) { v = ov; ix = oi; }
        }
        float v1 = v; int i1 = ix;
        float c0 = (lane == i1)      ? -INFINITY : l0;
        float c1 = (lane + 32 == i1) ? -INFINITY : l1;
        if (c1 > c0) { v = c1; ix = lane + 32; } else { v = c0; ix = lane; }
        #pragma unroll
        for (int off = 16; off; off >>= 1) {
            float ov = __shfl_xor_sync(0xffffffffu, v, off);
            int   oi = __shfl_xor_sync(0xffffffffu, ix, off);
            if (ov > v || (ov == v && oi < ix)) { v = ov; ix = oi; }
        }
        float v2 = v; int i2 = ix;
        if (lane == 0) {
            float q = expf(v2 - v1);
            g_topidx[2 * t]     = i1;
            g_topidx[2 * t + 1] = i2;
            g_topw[2 * t]       = 1.f / (1.f + q);
            g_topw[2 * t + 1]   = q / (1.f + q);
        }
    }
}

// ---------------- kernel 2: deterministic grouping + 32-token chunk table ----------------
__global__ __launch_bounds__(1024) void group_kernel() {
    __shared__ int cnt_s[NE], off_s[NE];
    int tid = threadIdx.x, lane = tid & 31, warp = tid >> 5;

    for (int e = warp; e < NE; e += 32) {
        int c = 0;
        for (int ch = 0; ch < NPAIR / 32; ch++) {
            int a = g_topidx[ch * 32 + lane];
            unsigned mask = __ballot_sync(0xffffffffu, a == e);
            c += __popc(mask);
        }
        if (lane == 0) cnt_s[e] = c;
    }
    __syncthreads();
    if (tid == 0) {
        int r = 0, nc = 0;
        for (int e = 0; e < NE; e++) {
            off_s[e] = r;
            int n = cnt_s[e];
            for (int t0 = 0; t0 < n; t0 += CH) {
                g_chunkE[nc] = e;
                g_chunkB[nc] = r + t0;
                g_chunkN[nc] = min(CH, n - t0);
                nc++;
            }
            r += n;
        }
        g_nch = nc;
    }
    __syncthreads();
    for (int e = warp; e < NE; e += 32) {
        int pos = off_s[e];
        for (int ch = 0; ch < NPAIR / 32; ch++) {
            int idx = ch * 32 + lane;
            int a = g_topidx[idx];
            unsigned mask = __ballot_sync(0xffffffffu, a == e);
            if (a == e) {
                int r = pos + __popc(mask & ((1u << lane) - 1u));
                g_rowTok[r] = idx;
                g_rowW[r]   = g_topw[idx];
            }
            pos += __popc(mask);
        }
    }
}

// ---------------- kernel 3: aux loss ----------------
__global__ __launch_bounds__(1024) void aux_kernel(float* auxp) {
    __shared__ float part[1024];
    int tid = threadIdx.x;
    int e = tid & 63, c = tid >> 6;
    float s = 0.f;
    int t0 = c * 32;
    for (int t = t0; t < t0 + 32; t++) s += g_probs[(size_t)t * NE + e];
    part[tid] = s;
    __syncthreads();
    if (tid < NE) {
        float tot = 0.f;
        for (int j = 0; j < 16; j++) tot += part[e + j * 64];
        part[tid] = tot * (64.0f / 512.0f);
    }
    __syncthreads();
    if (tid == 0 && auxp) {
        float m = 0.f;
        for (int i = 0; i < NE; i++) m += part[i];
        m *= (1.0f / 64.0f);
        float v = 0.f;
        for (int i = 0; i < NE; i++) { float d = part[i] - m; v += d * d; }
        auxp[0] = v * (1.0f / 63.0f);
    }
}

// ---------------- smem layouts (bytes) ----------------
// gateup: AH [2buf][2mat][64][KSTR] @0 (20480); AL @20480; BH [2][32][KSTR] @40960
//         (5120); BL @46080; TOK @51200 (128).  Total 51328.
#define GU_SMEM 51456
// down:   AH [2][64][KSTR] @0 (10240); AL @10240; BH @20480 (5120); BL @25600;
//         TOKF @30720 (128); WT @30848 (128).  Total 30976.
#define DN_SMEM 31104

// ---------------- kernel 4: gate/up, smem-pipelined mma.sync bf16 3-term ----------------
// grid (16 ftiles of 64, chunks), 128 thr (4 warps). K=512 in 16 stages of 32.
__global__ __launch_bounds__(128, 4) void gateup_mma(const float* __restrict__ wg,
                                                     const float* __restrict__ wu) {
    int c = blockIdx.y;
    if (c >= g_nch) return;
    int e = g_chunkE[c], rbase = g_chunkB[c], cnt = g_chunkN[c];
    int fblk = blockIdx.x * 64;

    extern __shared__ __align__(16) char smem[];
    int* tok_s = (int*)(smem + 51200);
    int tid = threadIdx.x, lane = tid & 31, warp = tid >> 5;
    int gq = lane >> 2, q2 = (lane & 3) * 2;

    if (tid < CH) tok_s[tid] = g_rowTok[rbase + min(tid, cnt - 1)] >> 1;
    __syncthreads();

    // A producer assignment: 8 float4 pieces over [2mat][64row][8pc]
    const float* srcA[8];
    int dstA[8];
    #pragma unroll
    for (int i = 0; i < 8; i++) {
        int p = i * 128 + tid;
        int mat = p >> 9, row = (p >> 3) & 63, pc = p & 7;
        srcA[i] = (mat ? wu : wg) + ((size_t)e * DE + fblk + row) * DM + pc * 4;
        dstA[i] = mat * 5120 + row * 80 + pc * 8;
    }
    // B cp.async assignment: j==0 -> hi, j==1 -> lo
    const __nv_bfloat16* srcB[2];
    int dstB[2];
    {
        int row = tid >> 2, pc = tid & 3;
        srcB[0] = g_xhi + (size_t)tok_s[row] * DM + pc * 8;
        srcB[1] = g_xlo + (size_t)tok_s[row] * DM + pc * 8;
        dstB[0] = 40960 + row * 80 + pc * 16;
        dstB[1] = 46080 + row * 80 + pc * 16;
    }

    float4 av[8];
    auto ldA = [&](int s) {
        int k0 = s * 32;
        #pragma unroll
        for (int i = 0; i < 8; i++) av[i] = *(const float4*)(srcA[i] + k0);
    };
    auto stA = [&](int b) {
        #pragma unroll
        for (int i = 0; i < 8; i++) {
            unsigned h0, h1, l0, l1;
            split4(av[i], h0, h1, l0, l1);
            int d = b * 10240 + dstA[i];
            *(uint2*)(smem + d)         = make_uint2(h0, h1);
            *(uint2*)(smem + 20480 + d) = make_uint2(l0, l1);
        }
    };
    auto ldB = [&](int s, int b) {
        int k0 = s * 32;
        cpa16(smem + dstB[0] + b * 2560, srcB[0] + k0);
        cpa16(smem + dstB[1] + b * 2560, srcB[1] + k0);
        CPA_COMMIT();
    };

    float dg[4][4], du[4][4];
    #pragma unroll
    for (int n = 0; n < 4; n++)
        #pragma unroll
        for (int r = 0; r < 4; r++) { dg[n][r] = 0.f; du[n][r] = 0.f; }

    int r0 = warp * 16 + gq, r1 = r0 + 8;

    ldA(0); ldB(0, 0); stA(0);
    CPA_WAIT0();
    __syncthreads();

    for (int s = 0; s < 16; s++) {
        int b = s & 1;
        if (s < 15) { ldA(s + 1); ldB(s + 1, b ^ 1); }

        #pragma unroll
        for (int kk = 0; kk < 32; kk += 16) {
            int kcb = (kk + q2) * 2;
            int aG = b * 10240, aU = aG + 5120;
            unsigned aghi[4], aglo[4], auhi[4], aulo[4];
            aghi[0] = *(unsigned*)(smem + aG + r0 * 80 + kcb);
            aghi[1] = *(unsigned*)(smem + aG + r1 * 80 + kcb);
            aghi[2] = *(unsigned*)(smem + aG + r0 * 80 + kcb + 16);
            aghi[3] = *(unsigned*)(smem + aG + r1 * 80 + kcb + 16);
            aglo[0] = *(unsigned*)(smem + 20480 + aG + r0 * 80 + kcb);
            aglo[1] = *(unsigned*)(smem + 20480 + aG + r1 * 80 + kcb);
            aglo[2] = *(unsigned*)(smem + 20480 + aG + r0 * 80 + kcb + 16);
            aglo[3] = *(unsigned*)(smem + 20480 + aG + r1 * 80 + kcb + 16);
            auhi[0] = *(unsigned*)(smem + aU + r0 * 80 + kcb);
            auhi[1] = *(unsigned*)(smem + aU + r1 * 80 + kcb);
            auhi[2] = *(unsigned*)(smem + aU + r0 * 80 + kcb + 16);
            auhi[3] = *(unsigned*)(smem + aU + r1 * 80 + kcb + 16);
            aulo[0] = *(unsigned*)(smem + 20480 + aU + r0 * 80 + kcb);
            aulo[1] = *(unsigned*)(smem + 20480 + aU + r1 * 80 + kcb);
            aulo[2] = *(unsigned*)(smem + 20480 + aU + r0 * 80 + kcb + 16);
            aulo[3] = *(unsigned*)(smem + 20480 + aU + r1 * 80 + kcb + 16);

            int bHb = 40960 + b * 2560, bLb = 46080 + b * 2560;
            #pragma unroll
            for (int n = 0; n < 4; n++) {
                int br = (n * 8 + gq) * 80;
                unsigned bhi[2], blo[2];
                bhi[0] = *(unsigned*)(smem + bHb + br + kcb);
                bhi[1] = *(unsigned*)(smem + bHb + br + kcb + 16);
                blo[0] = *(unsigned*)(smem + bLb + br + kcb);
                blo[1] = *(unsigned*)(smem + bLb + br + kcb + 16);
                mma16816(dg[n], aghi, bhi);
                mma16816(dg[n], aghi, blo);
                mma16816(dg[n], aglo, bhi);
                mma16816(du[n], auhi, bhi);
                mma16816(du[n], auhi, blo);
                mma16816(du[n], aulo, bhi);
            }
        }

        if (s < 15) stA(b ^ 1);
        CPA_WAIT0();
        __syncthreads();
    }

    // epilogue: h = silu(g)*u -> bf16 hi/lo
    int fbase = fblk + warp * 16;
    #pragma unroll
    for (int n = 0; n < 4; n++) {
        int t0 = n * 8 + q2;
        #pragma unroll
        for (int r = 0; r < 4; r++) {
            int tt = t0 + (r & 1);
            if (tt < cnt) {
                int f = fbase + gq + ((r >> 1) << 3);
                float gv = dg[n][r], uv = du[n][r];
                float hv = (gv / (1.f + expf(-gv))) * uv;
                __nv_bfloat16 hb = __float2bfloat16(hv);
                size_t idx = (size_t)(rbase + tt) * DE + f;
                g_hhi[idx] = hb;
                g_hlo[idx] = __float2bfloat16(hv - __bfloat162float(hb));
            }
        }
    }
}

// ---------------- kernel 5: down, smem-pipelined + weighted scatter ----------------
// grid (8 dtiles of 64, chunks), 128 thr. K=1024 in 32 stages of 32.
__global__ __launch_bounds__(128, 4) void down_mma(const float* __restrict__ wd,
                                                   float* __restrict__ out) {
    int c = blockIdx.y;
    if (c >= g_nch) return;
    int e = g_chunkE[c], rbase = g_chunkB[c], cnt = g_chunkN[c];
    int dblk = blockIdx.x * 64;

    extern __shared__ __align__(16) char smem[];
    int*   tokf_s = (int*)(smem + 30720);
    float* wt_s   = (float*)(smem + 30848);
    int tid = threadIdx.x, lane = tid & 31, warp = tid >> 5;
    int gq = lane >> 2, q2 = (lane & 3) * 2;

    if (tid < CH) {
        int rr = rbase + min(tid, cnt - 1);
        tokf_s[tid] = g_rowTok[rr];
        wt_s[tid]   = g_rowW[rr];
    }
    __syncthreads();

    // A producer: 4 float4 pieces over [64row][8pc]
    const float* srcA[4];
    int dstA[4];
    #pragma unroll
    for (int i = 0; i < 4; i++) {
        int p = i * 128 + tid;
        int row = p >> 3, pc = p & 7;
        srcA[i] = wd + ((size_t)e * DM + dblk + row) * DE + pc * 4;
        dstA[i] = row * 80 + pc * 8;
    }
    const __nv_bfloat16* srcB[2];
    int dstB[2];
    {
        int row = tid >> 2, pc = tid & 3;
        size_t hrow = (size_t)(rbase + min(row, cnt - 1)) * DE;
        srcB[0] = g_hhi + hrow + pc * 8;
        srcB[1] = g_hlo + hrow + pc * 8;
        dstB[0] = 20480 + row * 80 + pc * 16;
        dstB[1] = 25600 + row * 80 + pc * 16;
    }

    float4 av[4];
    auto ldA = [&](int s) {
        int k0 = s * 32;
        #pragma unroll
        for (int i = 0; i < 4; i++) av[i] = *(const float4*)(srcA[i] + k0);
    };
    auto stA = [&](int b) {
        #pragma unroll
        for (int i = 0; i < 4; i++) {
            unsigned h0, h1, l0, l1;
            split4(av[i], h0, h1, l0, l1);
            int d = b * 5120 + dstA[i];
            *(uint2*)(smem + d)         = make_uint2(h0, h1);
            *(uint2*)(smem + 10240 + d) = make_uint2(l0, l1);
        }
    };
    auto ldB = [&](int s, int b) {
        int k0 = s * 32;
        cpa16(smem + dstB[0] + b * 2560, srcB[0] + k0);
        cpa16(smem + dstB[1] + b * 2560, srcB[1] + k0);
        CPA_COMMIT();
    };

    float acc[4][4];
    #pragma unroll
    for (int n = 0; n < 4; n++)
        #pragma unroll
        for (int r = 0; r < 4; r++) acc[n][r] = 0.f;

    int r0 = warp * 16 + gq, r1 = r0 + 8;

    ldA(0); ldB(0, 0); stA(0);
    CPA_WAIT0();
    __syncthreads();

    for (int s = 0; s < 32; s++) {
        int b = s & 1;
        if (s < 31) { ldA(s + 1); ldB(s + 1, b ^ 1); }

        #pragma unroll
        for (int kk = 0; kk < 32; kk += 16) {
            int kcb = (kk + q2) * 2;
            int aB = b * 5120;
            unsigned ahi[4], alo[4];
            ahi[0] = *(unsigned*)(smem + aB + r0 * 80 + kcb);
            ahi[1] = *(unsigned*)(smem + aB + r1 * 80 + kcb);
            ahi[2] = *(unsigned*)(smem + aB + r0 * 80 + kcb + 16);
            ahi[3] = *(unsigned*)(smem + aB + r1 * 80 + kcb + 16);
            alo[0] = *(unsigned*)(smem + 10240 + aB + r0 * 80 + kcb);
            alo[1] = *(unsigned*)(smem + 10240 + aB + r1 * 80 + kcb);
            alo[2] = *(unsigned*)(smem + 10240 + aB + r0 * 80 + kcb + 16);
            alo[3] = *(unsigned*)(smem + 10240 + aB + r1 * 80 + kcb + 16);

            int bHb = 20480 + b * 2560, bLb = 25600 + b * 2560;
            #pragma unroll
            for (int n = 0; n < 4; n++) {
                int br = (n * 8 + gq) * 80;
                unsigned bhi[2], blo[2];
                bhi[0] = *(unsigned*)(smem + bHb + br + kcb);
                bhi[1] = *(unsigned*)(smem + bHb + br + kcb + 16);
                blo[0] = *(unsigned*)(smem + bLb + br + kcb);
                blo[1] = *(unsigned*)(smem + bLb + br + kcb + 16);
                mma16816(acc[n], ahi, bhi);
                mma16816(acc[n], ahi, blo);
                mma16816(acc[n], alo, bhi);
            }
        }

        if (s < 31) stA(b ^ 1);
        CPA_WAIT0();
        __syncthreads();
    }

    int dbase = dblk + warp * 16;
    #pragma unroll
    for (int n = 0; n < 4; n++) {
        int t0 = n * 8 + q2;
        #pragma unroll
        for (int r = 0; r < 4; r++) {
            int tt = t0 + (r & 1);
            if (tt < cnt) {
                int d = dbase + gq + ((r >> 1) << 3);
                int tok = tokf_s[tt] >> 1;
                atomicAdd(out + (size_t)tok * DM + d, wt_s[tt] * acc[n][r]);
            }
        }
    }
}

// ---------------- launch ----------------
extern "C" void kernel_launch(void* const* d_in, const int* in_sizes, int n_in,
                              void* d_out, int out_size) {
    const float* x  = (const float*)d_in[0];
    const float* rw = (const float*)d_in[1];
    const float* wg = (const float*)d_in[2];
    const float* wu = (const float*)d_in[3];
    const float* wd = (const float*)d_in[4];
    float* out = (float*)d_out;

    cudaMemsetAsync(d_out, 0, (size_t)out_size * sizeof(float), 0);

    xcvt_kernel<<<T_TOK * DM / 4 / 256, 256>>>(x);
    router_kernel<<<T_TOK / 4, 256>>>(x, rw);
    group_kernel<<<1, 1024>>>();

    float* auxp = (out_size > T_TOK * DM) ? out + (size_t)T_TOK * DM : nullptr;
    aux_kernel<<<1, 1024>>>(auxp);

    cudaFuncSetAttribute(gateup_mma, cudaFuncAttributeMaxDynamicSharedMemorySize, GU_SMEM);
    cudaFuncSetAttribute(down_mma,   cudaFuncAttributeMaxDynamicSharedMemorySize, DN_SMEM);

    gateup_mma<<<dim3(16, CHMAX), 128, GU_SMEM>>>(wg, wu);
    down_mma<<<dim3(8, CHMAX), 128, DN_SMEM>>>(wd, out);
}

// round 15
// speedup vs baseline: 1.0803x; 1.0803x over previous
#include <cuda_runtime.h>
#include <cuda_bf16.h>
#include <math.h>

#define T_TOK 512
#define DM    512
#define DE    1024
#define NE    64
#define NPAIR 1024
#define CHMAX 128
#define CH    32

// ---------------- scratch (static device globals; no allocation) ----------------
__device__ int   g_topidx[NPAIR];
__device__ float g_topw[NPAIR];
__device__ int   g_rowTok[NPAIR];
__device__ float g_rowW[NPAIR];
__device__ int   g_chunkE[CHMAX], g_chunkB[CHMAX], g_chunkN[CHMAX];
__device__ int   g_nch;
__device__ float g_ps[128 * NE];                 // per-block prob partial sums
__device__ __nv_bfloat16 g_xhi[T_TOK * DM];
__device__ __nv_bfloat16 g_xlo[T_TOK * DM];
__device__ __nv_bfloat16 g_hhi[(size_t)NPAIR * DE];
__device__ __nv_bfloat16 g_hlo[(size_t)NPAIR * DE];

// ---------------- helpers ----------------
__device__ __forceinline__ unsigned pkbf2(float lo, float hi) {
    unsigned r;
    asm("cvt.rn.bf16x2.f32 %0, %1, %2;" : "=r"(r) : "f"(hi), "f"(lo));
    return r;
}
__device__ __forceinline__ void split4(float4 v, unsigned& h0, unsigned& h1,
                                       unsigned& l0, unsigned& l1) {
    h0 = pkbf2(v.x, v.y);
    h1 = pkbf2(v.z, v.w);
    float rx = v.x - __uint_as_float(h0 << 16);
    float ry = v.y - __uint_as_float(h0 & 0xffff0000u);
    float rz = v.z - __uint_as_float(h1 << 16);
    float rw = v.w - __uint_as_float(h1 & 0xffff0000u);
    l0 = pkbf2(rx, ry);
    l1 = pkbf2(rz, rw);
}
__device__ __forceinline__ void split2(float2 v, unsigned& hi, unsigned& lo) {
    hi = pkbf2(v.x, v.y);
    float rx = v.x - __uint_as_float(hi << 16);
    float ry = v.y - __uint_as_float(hi & 0xffff0000u);
    lo = pkbf2(rx, ry);
}
__device__ __forceinline__ void mma16816(float* d, const unsigned* a, const unsigned* b) {
    asm volatile(
        "mma.sync.aligned.m16n8k16.row.col.f32.bf16.bf16.f32 "
        "{%0,%1,%2,%3}, {%4,%5,%6,%7}, {%8,%9}, {%0,%1,%2,%3};"
        : "+f"(d[0]), "+f"(d[1]), "+f"(d[2]), "+f"(d[3])
        : "r"(a[0]), "r"(a[1]), "r"(a[2]), "r"(a[3]), "r"(b[0]), "r"(b[1]));
}
__device__ __forceinline__ void cpa16(char* smem_dst, const void* gsrc) {
    unsigned a = (unsigned)__cvta_generic_to_shared(smem_dst);
    asm volatile("cp.async.cg.shared.global [%0], [%1], 16;" :: "r"(a), "l"(gsrc));
}
#define CPA_COMMIT() asm volatile("cp.async.commit_group;" ::: "memory")
#define CPA_WAITG2() asm volatile("cp.async.wait_group 2;" ::: "memory")

// ---------------- kernel 1: router + x-convert (4 tokens per block) ----------------
__global__ __launch_bounds__(256) void router_kernel(const float* __restrict__ x,
                                                     const float* __restrict__ rw) {
    __shared__ float xs[4 * DM];
    __shared__ float lg[4 * NE];
    __shared__ float ps[4 * NE];
    int tid = threadIdx.x, lane = tid & 31, warp = tid >> 5;
    int tbase = blockIdx.x * 4;

    for (int i = tid; i < 4 * DM / 4; i += 256)
        *(float4*)(xs + i * 4) = *(const float4*)(x + (size_t)tbase * DM + i * 4);
    __syncthreads();

    // fold xcvt: convert this block's 4 tokens to bf16 hi/lo
    #pragma unroll
    for (int j = 0; j < 2; j++) {
        int i = tid * 2 + j;                       // 0..511 float4s
        float4 v = *(const float4*)(xs + i * 4);
        unsigned h0, h1, l0, l1;
        split4(v, h0, h1, l0, l1);
        size_t g = (size_t)tbase * 128 + i;
        ((uint2*)g_xhi)[g] = make_uint2(h0, h1);
        ((uint2*)g_xlo)[g] = make_uint2(l0, l1);
    }

    for (int j = 0; j < 8; j++) {
        int e = warp * 8 + j;
        const float* w = rw + (size_t)e * DM;
        float acc[4] = {0.f, 0.f, 0.f, 0.f};
        #pragma unroll
        for (int q = 0; q < 4; q++) {
            float4 wv = *(const float4*)(w + (size_t)(lane + 32 * q) * 4);
            int kb = (lane + 32 * q) * 4;
            #pragma unroll
            for (int t = 0; t < 4; t++) {
                acc[t] += wv.x * xs[t * DM + kb + 0];
                acc[t] += wv.y * xs[t * DM + kb + 1];
                acc[t] += wv.z * xs[t * DM + kb + 2];
                acc[t] += wv.w * xs[t * DM + kb + 3];
            }
        }
        #pragma unroll
        for (int t = 0; t < 4; t++) {
            float a = acc[t];
            #pragma unroll
            for (int off = 16; off; off >>= 1) a += __shfl_xor_sync(0xffffffffu, a, off);
            if (lane == 0) lg[t * NE + e] = a;
        }
    }
    __syncthreads();

    if (warp < 4) {
        int tl = warp;
        int t = tbase + tl;
        float l0 = lg[tl * NE + lane];
        float l1 = lg[tl * NE + lane + 32];
        float m = fmaxf(l0, l1);
        #pragma unroll
        for (int off = 16; off; off >>= 1) m = fmaxf(m, __shfl_xor_sync(0xffffffffu, m, off));
        float p0 = expf(l0 - m), p1 = expf(l1 - m);
        float s = p0 + p1;
        #pragma unroll
        for (int off = 16; off; off >>= 1) s += __shfl_xor_sync(0xffffffffu, s, off);
        ps[tl * NE + lane]      = p0 / s;
        ps[tl * NE + lane + 32] = p1 / s;

        float v; int ix;
        if (l1 > l0) { v = l1; ix = lane + 32; } else { v = l0; ix = lane; }
        #pragma unroll
        for (int off = 16; off; off >>= 1) {
            float ov = __shfl_xor_sync(0xffffffffu, v, off);
            int   oi = __shfl_xor_sync(0xffffffffu, ix, off);
            if (ov > v || (ov == v && oi < ix)) { v = ov; ix = oi; }
        }
        float v1 = v; int i1 = ix;
        float c0 = (lane == i1)      ? -INFINITY : l0;
        float c1 = (lane + 32 == i1) ? -INFINITY : l1;
        if (c1 > c0) { v = c1; ix = lane + 32; } else { v = c0; ix = lane; }
        #pragma unroll
        for (int off = 16; off; off >>= 1) {
            float ov = __shfl_xor_sync(0xffffffffu, v, off);
            int   oi = __shfl_xor_sync(0xffffffffu, ix, off);
            if (ov > v || (ov == v && oi < ix)) { v = ov; ix = oi; }
        }
        float v2 = v; int i2 = ix;
        if (lane == 0) {
            float q = expf(v2 - v1);
            g_topidx[2 * t]     = i1;
            g_topidx[2 * t + 1] = i2;
            g_topw[2 * t]       = 1.f / (1.f + q);
            g_topw[2 * t + 1]   = q / (1.f + q);
        }
    }
    __syncthreads();
    if (tid < NE) {
        float s4 = ps[tid] + ps[NE + tid] + ps[2 * NE + tid] + ps[3 * NE + tid];
        g_ps[blockIdx.x * NE + tid] = s4;
    }
}

// ---------------- kernel 2: grouping + chunk table + aux loss (1 block) ----------------
__global__ __launch_bounds__(1024) void group_kernel(float* auxp) {
    __shared__ int cnt_s[NE], off_s[NE];
    __shared__ float vals[NE];
    int tid = threadIdx.x, lane = tid & 31, warp = tid >> 5;

    // aux: sum per-block partials, scale by E/T = 64/512 = 1/8
    if (tid < NE) {
        float s = 0.f;
        for (int b = 0; b < 128; b++) s += g_ps[b * NE + tid];
        vals[tid] = s * 0.125f;
    }

    for (int e = warp; e < NE; e += 32) {
        int c = 0;
        for (int ch = 0; ch < NPAIR / 32; ch++) {
            int a = g_topidx[ch * 32 + lane];
            unsigned mask = __ballot_sync(0xffffffffu, a == e);
            c += __popc(mask);
        }
        if (lane == 0) cnt_s[e] = c;
    }
    __syncthreads();
    if (tid == 0) {
        int r = 0, nc = 0;
        for (int e = 0; e < NE; e++) {
            off_s[e] = r;
            int n = cnt_s[e];
            for (int t0 = 0; t0 < n; t0 += CH) {
                g_chunkE[nc] = e;
                g_chunkB[nc] = r + t0;
                g_chunkN[nc] = min(CH, n - t0);
                nc++;
            }
            r += n;
        }
        g_nch = nc;
    }
    if (tid == 32 && auxp) {   // different warp than the serial scan above
        float m = 0.f;
        for (int i = 0; i < NE; i++) m += vals[i];
        m *= (1.0f / 64.0f);
        float v = 0.f;
        for (int i = 0; i < NE; i++) { float d = vals[i] - m; v += d * d; }
        auxp[0] = v * (1.0f / 63.0f);
    }
    __syncthreads();
    for (int e = warp; e < NE; e += 32) {
        int pos = off_s[e];
        for (int ch = 0; ch < NPAIR / 32; ch++) {
            int idx = ch * 32 + lane;
            int a = g_topidx[idx];
            unsigned mask = __ballot_sync(0xffffffffu, a == e);
            if (a == e) {
                int r = pos + __popc(mask & ((1u << lane) - 1u));
                g_rowTok[r] = idx;
                g_rowW[r]   = g_topw[idx];
            }
            pos += __popc(mask);
        }
    }
}

// ---------------- smem layouts (bytes), ring = 3 stages ----------------
// gateup: A fp32 [3][2 mats][64 rows][36 f] @0 (stage 18432, tot 55296);
//         BH bf16 [3][32][40] @55296 (stage 2560, tot 7680); BL @62976; TOK @70656
#define GU_AST  18432
#define GU_BH   55296
#define GU_BL   62976
#define GU_TOK  70656
#define GU_SMEM 70784
// down:   A fp32 [3][64][36] @0 (stage 9216, tot 27648); BH @27648; BL @35328;
//         TOKF @43008; WT @43136
#define DN_AST  9216
#define DN_BH   27648
#define DN_BL   35328
#define DN_TOKF 43008
#define DN_WT   43136
#define DN_SMEM 43264

// ---------------- kernel 3: gate/up, cp.async-ring mma.sync bf16 3-term ----------------
// grid (16 ftiles of 64, chunks), 128 thr (4 warps). K=512 in 16 stages of 32.
__global__ __launch_bounds__(128, 3) void gateup_mma(const float* __restrict__ wg,
                                                     const float* __restrict__ wu) {
    int c = blockIdx.y;
    if (c >= g_nch) return;
    int e = g_chunkE[c], rbase = g_chunkB[c], cnt = g_chunkN[c];
    int fblk = blockIdx.x * 64;

    extern __shared__ __align__(16) char smem[];
    int* tok_s = (int*)(smem + GU_TOK);
    int tid = threadIdx.x, lane = tid & 31, warp = tid >> 5;
    int gq = lane >> 2, q2 = (lane & 3) * 2;

    if (tid < CH) tok_s[tid] = g_rowTok[rbase + min(tid, cnt - 1)] >> 1;
    __syncthreads();

    // A producer: 8 float4 pieces over [2 mats][64 rows][8 pc]
    const float* srcA[8];
    int dstA[8];
    #pragma unroll
    for (int i = 0; i < 8; i++) {
        int p = i * 128 + tid;
        int mat = p >> 9, rem = p & 511, row = rem >> 3, pc = rem & 7;
        srcA[i] = (mat ? wu : wg) + ((size_t)e * DE + fblk + row) * DM + pc * 4;
        dstA[i] = mat * 9216 + row * 144 + pc * 16;
    }
    const __nv_bfloat16* srcB[2];
    int dstB[2];
    {
        int row = tid >> 2, pc = tid & 3;
        srcB[0] = g_xhi + (size_t)tok_s[row] * DM + pc * 8;
        srcB[1] = g_xlo + (size_t)tok_s[row] * DM + pc * 8;
        dstB[0] = GU_BH + row * 80 + pc * 16;
        dstB[1] = GU_BL + row * 80 + pc * 16;
    }

    auto fill = [&](int s) {
        int st = (s % 3);
        int k0 = s * 32;
        #pragma unroll
        for (int i = 0; i < 8; i++)
            cpa16(smem + st * GU_AST + dstA[i], srcA[i] + k0);
        cpa16(smem + dstB[0] + st * 2560, srcB[0] + k0);
        cpa16(smem + dstB[1] + st * 2560, srcB[1] + k0);
    };

    float dg[4][4], du[4][4];
    #pragma unroll
    for (int n = 0; n < 4; n++)
        #pragma unroll
        for (int r = 0; r < 4; r++) { dg[n][r] = 0.f; du[n][r] = 0.f; }

    int r0 = warp * 16 + gq;
    int aoff0 = r0 * 144, aoff1 = (r0 + 8) * 144;

    fill(0); CPA_COMMIT();
    fill(1); CPA_COMMIT();
    fill(2); CPA_COMMIT();

    for (int s = 0; s < 16; s++) {
        int st = s % 3;
        CPA_WAITG2();
        __syncthreads();

        const char* aB = smem + st * GU_AST;
        const char* bH = smem + GU_BH + st * 2560;
        const char* bL = smem + GU_BL + st * 2560;

        #pragma unroll
        for (int kk = 0; kk < 32; kk += 16) {
            int kb = (kk + q2) * 4;
            unsigned aghi[4], aglo[4], auhi[4], aulo[4];
            split2(*(const float2*)(aB + aoff0 + kb),        aghi[0], aglo[0]);
            split2(*(const float2*)(aB + aoff1 + kb),        aghi[1], aglo[1]);
            split2(*(const float2*)(aB + aoff0 + kb + 32),   aghi[2], aglo[2]);
            split2(*(const float2*)(aB + aoff1 + kb + 32),   aghi[3], aglo[3]);
            split2(*(const float2*)(aB + 9216 + aoff0 + kb),      auhi[0], aulo[0]);
            split2(*(const float2*)(aB + 9216 + aoff1 + kb),      auhi[1], aulo[1]);
            split2(*(const float2*)(aB + 9216 + aoff0 + kb + 32), auhi[2], aulo[2]);
            split2(*(const float2*)(aB + 9216 + aoff1 + kb + 32), auhi[3], aulo[3]);

            int kcb = (kk + q2) * 2;
            #pragma unroll
            for (int n = 0; n < 4; n++) {
                int br = (n * 8 + gq) * 80;
                unsigned bhi[2], blo[2];
                bhi[0] = *(const unsigned*)(bH + br + kcb);
                bhi[1] = *(const unsigned*)(bH + br + kcb + 16);
                blo[0] = *(const unsigned*)(bL + br + kcb);
                blo[1] = *(const unsigned*)(bL + br + kcb + 16);
                mma16816(dg[n], aghi, bhi);
                mma16816(dg[n], aghi, blo);
                mma16816(dg[n], aglo, bhi);
                mma16816(du[n], auhi, bhi);
                mma16816(du[n], auhi, blo);
                mma16816(du[n], aulo, bhi);
            }
        }

        __syncthreads();
        if (s + 3 < 16) fill(s + 3);
        CPA_COMMIT();
    }

    // epilogue: h = silu(g)*u -> bf16 hi/lo
    int fbase = fblk + warp * 16;
    #pragma unroll
    for (int n = 0; n < 4; n++) {
        int t0 = n * 8 + q2;
        #pragma unroll
        for (int r = 0; r < 4; r++) {
            int tt = t0 + (r & 1);
            if (tt < cnt) {
                int f = fbase + gq + ((r >> 1) << 3);
                float gv = dg[n][r], uv = du[n][r];
                float hv = (gv / (1.f + expf(-gv))) * uv;
                __nv_bfloat16 hb = __float2bfloat16(hv);
                size_t idx = (size_t)(rbase + tt) * DE + f;
                g_hhi[idx] = hb;
                g_hlo[idx] = __float2bfloat16(hv - __bfloat162float(hb));
            }
        }
    }
}

// ---------------- kernel 4: down, cp.async-ring + weighted scatter ----------------
// grid (8 dtiles of 64, chunks), 128 thr. K=1024 in 32 stages of 32.
__global__ __launch_bounds__(128, 4) void down_mma(const float* __restrict__ wd,
                                                   float* __restrict__ out) {
    int c = blockIdx.y;
    if (c >= g_nch) return;
    int e = g_chunkE[c], rbase = g_chunkB[c], cnt = g_chunkN[c];
    int dblk = blockIdx.x * 64;

    extern __shared__ __align__(16) char smem[];
    int*   tokf_s = (int*)(smem + DN_TOKF);
    float* wt_s   = (float*)(smem + DN_WT);
    int tid = threadIdx.x, lane = tid & 31, warp = tid >> 5;
    int gq = lane >> 2, q2 = (lane & 3) * 2;

    if (tid < CH) {
        int rr = rbase + min(tid, cnt - 1);
        tokf_s[tid] = g_rowTok[rr];
        wt_s[tid]   = g_rowW[rr];
    }
    __syncthreads();

    const float* srcA[4];
    int dstA[4];
    #pragma unroll
    for (int i = 0; i < 4; i++) {
        int p = i * 128 + tid;
        int row = p >> 3, pc = p & 7;
        srcA[i] = wd + ((size_t)e * DM + dblk + row) * DE + pc * 4;
        dstA[i] = row * 144 + pc * 16;
    }
    const __nv_bfloat16* srcB[2];
    int dstB[2];
    {
        int row = tid >> 2, pc = tid & 3;
        size_t hrow = (size_t)(rbase + min(row, cnt - 1)) * DE;
        srcB[0] = g_hhi + hrow + pc * 8;
        srcB[1] = g_hlo + hrow + pc * 8;
        dstB[0] = DN_BH + row * 80 + pc * 16;
        dstB[1] = DN_BL + row * 80 + pc * 16;
    }

    auto fill = [&](int s) {
        int st = (s % 3);
        int k0 = s * 32;
        #pragma unroll
        for (int i = 0; i < 4; i++)
            cpa16(smem + st * DN_AST + dstA[i], srcA[i] + k0);
        cpa16(smem + dstB[0] + st * 2560, srcB[0] + k0);
        cpa16(smem + dstB[1] + st * 2560, srcB[1] + k0);
    };

    float acc[4][4];
    #pragma unroll
    for (int n = 0; n < 4; n++)
        #pragma unroll
        for (int r = 0; r < 4; r++) acc[n][r] = 0.f;

    int r0 = warp * 16 + gq;
    int aoff0 = r0 * 144, aoff1 = (r0 + 8) * 144;

    fill(0); CPA_COMMIT();
    fill(1); CPA_COMMIT();
    fill(2); CPA_COMMIT();

    for (int s = 0; s < 32; s++) {
        int st = s % 3;
        CPA_WAITG2();
        __syncthreads();

        const char* aB = smem + st * DN_AST;
        const char* bH = smem + DN_BH + st * 2560;
        const char* bL = smem + DN_BL + st * 2560;

        #pragma unroll
        for (int kk = 0; kk < 32; kk += 16) {
            int kb = (kk + q2) * 4;
            unsigned ahi[4], alo[4];
            split2(*(const float2*)(aB + aoff0 + kb),      ahi[0], alo[0]);
            split2(*(const float2*)(aB + aoff1 + kb),      ahi[1], alo[1]);
            split2(*(const float2*)(aB + aoff0 + kb + 32), ahi[2], alo[2]);
            split2(*(const float2*)(aB + aoff1 + kb + 32), ahi[3], alo[3]);

            int kcb = (kk + q2) * 2;
            #pragma unroll
            for (int n = 0; n < 4; n++) {
                int br = (n * 8 + gq) * 80;
                unsigned bhi[2], blo[2];
                bhi[0] = *(const unsigned*)(bH + br + kcb);
                bhi[1] = *(const unsigned*)(bH + br + kcb + 16);
                blo[0] = *(const unsigned*)(bL + br + kcb);
                blo[1] = *(const unsigned*)(bL + br + kcb + 16);
                mma16816(acc[n], ahi, bhi);
                mma16816(acc[n], ahi, blo);
                mma16816(acc[n], alo, bhi);
            }
        }

        __syncthreads();
        if (s + 3 < 32) fill(s + 3);
        CPA_COMMIT();
    }

    int dbase = dblk + warp * 16;
    #pragma unroll
    for (int n = 0; n < 4; n++) {
        int t0 = n * 8 + q2;
        #pragma unroll
        for (int r = 0; r < 4; r++) {
            int tt = t0 + (r & 1);
            if (tt < cnt) {
                int d = dbase + gq + ((r >> 1) << 3);
                int tok = tokf_s[tt] >> 1;
                atomicAdd(out + (size_t)tok * DM + d, wt_s[tt] * acc[n][r]);
            }
        }
    }
}

// ---------------- launch ----------------
extern "C" void kernel_launch(void* const* d_in, const int* in_sizes, int n_in,
                              void* d_out, int out_size) {
    const float* x  = (const float*)d_in[0];
    const float* rw = (const float*)d_in[1];
    const float* wg = (const float*)d_in[2];
    const float* wu = (const float*)d_in[3];
    const float* wd = (const float*)d_in[4];
    float* out = (float*)d_out;

    cudaMemsetAsync(d_out, 0, (size_t)out_size * sizeof(float), 0);

    router_kernel<<<T_TOK / 4, 256>>>(x, rw);

    float* auxp = (out_size > T_TOK * DM) ? out + (size_t)T_TOK * DM : nullptr;
    group_kernel<<<1, 1024>>>(auxp);

    cudaFuncSetAttribute(gateup_mma, cudaFuncAttributeMaxDynamicSharedMemorySize, GU_SMEM);
    cudaFuncSetAttribute(down_mma,   cudaFuncAttributeMaxDynamicSharedMemorySize, DN_SMEM);

    gateup_mma<<<dim3(16, CHMAX), 128, GU_SMEM>>>(wg, wu);
    down_mma<<<dim3(8, CHMAX), 128, DN_SMEM>>>(wd, out);
}